// round 12
// baseline (speedup 1.0000x reference)
#include <cuda_runtime.h>
#include <cstdint>
#include <math.h>

// CTRNN B=128, N=512, T=1024, fp32.
// R11: 512 CTAs of 128 threads (16 batch groups x 32 hidden ranks, IS=16),
// 4 CTAs/SM co-residency (54.7KB smem, <=128 regs). Per-warp j-chunk (128 j)
// exchange: ballot-poll of 8 source ranks, stage, GEMM (256 FFMA2 + 160 LDS
// per warp), ONE syncthreads/step, warp-granular counter release, rotating
// out-writer (rank t&31, lag 2, quad-buffered g_part).

#define T_STEPS 1024
#define BATCH   128
#define NH      512
#define DTC     0.02f

#define NR   32                 // hidden ranks (IS = 16)
#define NG   16                 // batch groups (BS = 8)
#define BS   8
#define IS   16
#define NCTA (NG * NR)          // 512
#define NTHR 128
#define KW   4                  // j-chunks, one per warp
#define KCH  128                // j's per warp (= 8 source ranks)
#define LDP  516
#define RB   20                 // red row pad (perfect bank spread)

// smem float offsets
#define OFF_J   0                          // 16 x 516 = 8256
#define OFF_TH  (OFF_J + IS * LDP)         // 8 x 516 -> 12384
#define OFF_RED (OFF_TH + BS * LDP)        // [2][KW][BS][RB] = 1280
#define SMEM_FLOATS (OFF_RED + 2 * KW * BS * RB)
#define SMEM_BYTES  (SMEM_FLOATS * 4)      // 54656 B -> 4 CTAs/SM

__device__ float g_th[2][BATCH][NH];        // tanh(h) double buffer (L2)
__device__ float g_part[4][NG][NR][BS];     // readout partials, quad buffer
__device__ int   g_cnt[NG][NR][32];         // 128B-strided warp-publish counters

__device__ __forceinline__ unsigned long long ffma2(unsigned long long a,
                                                    unsigned long long b,
                                                    unsigned long long c) {
    unsigned long long d;
    asm("fma.rn.f32x2 %0, %1, %2, %3;" : "=l"(d) : "l"(a), "l"(b), "l"(c));
    return d;
}

__device__ __forceinline__ float2 unpack2(unsigned long long v) {
    float2 f;
    asm("mov.b64 {%0, %1}, %2;" : "=f"(f.x), "=f"(f.y) : "l"(v));
    return f;
}

__device__ __forceinline__ float fast_tanh(float x) {
    float e = __expf(2.0f * x);
    return 1.0f - __fdividef(2.0f, e + 1.0f);
}

__device__ __forceinline__ int ld_acq(const int* p) {
    int v;
    asm volatile("ld.acquire.gpu.global.s32 %0, [%1];" : "=r"(v) : "l"(p) : "memory");
    return v;
}

__device__ __forceinline__ void red_add_gpu(int* p, int v) {
    asm volatile("red.relaxed.gpu.global.add.s32 [%0], %1;" :: "l"(p), "r"(v) : "memory");
}

__device__ __forceinline__ void fence_gpu() {
    asm volatile("fence.acq_rel.gpu;" ::: "memory");
}

extern "C" __global__ void __launch_bounds__(NTHR, 4)
ctrnn_r11_kernel(const float* __restrict__ vel,
                 const float* __restrict__ J,
                 const float* __restrict__ Bmat,
                 const float* __restrict__ Wro,
                 float* __restrict__ out) {
    extern __shared__ float smem[];
    float* J_s  = smem + OFF_J;
    float* th_s = smem + OFF_TH;
    float* red  = smem + OFF_RED;   // [2][KW][BS][RB]

    const int tid  = threadIdx.x;
    const int rank = blockIdx.x & (NR - 1);
    const int grp  = blockIdx.x >> 5;
    const int b0   = grp * BS;
    const int i0   = rank * IS;

    // One-time: J slice [IS x NH] into padded smem; zero th_s (tanh(0)=0).
    for (int k4 = tid; k4 < IS * NH / 4; k4 += NTHR) {
        int idx = k4 * 4, r = idx >> 9, c = idx & 511;
        *reinterpret_cast<float4*>(J_s + r * LDP + c) =
            *reinterpret_cast<const float4*>(J + (size_t)(i0 + r) * NH + c);
    }
    for (int k4 = tid; k4 < BS * NH / 4; k4 += NTHR) {
        int idx = k4 * 4, r = idx >> 9, c = idx & 511;
        *reinterpret_cast<float4*>(th_s + r * LDP + c) = make_float4(0.f, 0.f, 0.f, 0.f);
    }
    // Monotonic counter base (all counters equal at every launch boundary).
    const int base = __ldcg(&g_cnt[grp][rank][0]);
    __syncthreads();

    const int w = tid >> 5, lane = tid & 31;
    const int bg = lane & 7, ig = lane >> 3;      // GEMM tile: row bg, cols ig+4v
    const int kbase = w * KCH;
    const int b = tid >> 4, i = tid & 15;         // reduce/publish ownership
    const float bmv = Bmat[i0 + i];
    const float wrv = Wro[i0 + i];
    const int* fPoll = &g_cnt[grp][8 * w + (lane & 7)][0];  // lanes 0..7 active
    int* fOwn = &g_cnt[grp][rank][0];
    float h = 0.f;

    for (int t = 0; t < T_STEPS; ++t) {
        const int p = t & 1;
        float* redw = red + p * (KW * BS * RB);

        // Prefetch vel (consumed after the barrier).
        const float vt = vel[(size_t)(b0 + b) * T_STEPS + t];

        // ---- per-warp ballot-poll of 8 source ranks + stage j-chunk ----
        if (t > 0) {
            const int tgt = base + 4 * t;
            int myv;
            do {
                myv = (lane < 8) ? ld_acq(fPoll) : tgt;
            } while (__any_sync(0xffffffffu, myv < tgt));

            const float* src = &g_th[(t - 1) & 1][b0][0] + kbase + lane * 4;
            float4 v[8];
            #pragma unroll
            for (int q = 0; q < 8; ++q)
                v[q] = __ldcg(reinterpret_cast<const float4*>(src + (size_t)q * NH));
            #pragma unroll
            for (int q = 0; q < 8; ++q)
                *reinterpret_cast<float4*>(th_s + q * LDP + kbase + lane * 4) = v[q];
            __syncwarp();
        }

        // ---- GEMM: redw[w][bg][ig+4v] = sum_{j in chunk w} th[bg][j]*J[i][j]
        unsigned long long acc[4] = {0ull, 0ull, 0ull, 0ull};
        #pragma unroll 8
        for (int jt = 0; jt < KCH; jt += 4) {
            const int j = kbase + jt;
            ulonglong2 av = *reinterpret_cast<const ulonglong2*>(th_s + bg * LDP + j);
            ulonglong2 bv[4];
            #pragma unroll
            for (int v = 0; v < 4; ++v)
                bv[v] = *reinterpret_cast<const ulonglong2*>(J_s + (ig + 4 * v) * LDP + j);
            #pragma unroll
            for (int v = 0; v < 4; ++v) {
                acc[v] = ffma2(av.x, bv[v].x, acc[v]);
                acc[v] = ffma2(av.y, bv[v].y, acc[v]);
            }
        }
        #pragma unroll
        for (int v = 0; v < 4; ++v) {
            float2 f2 = unpack2(acc[v]);
            redw[w * (BS * RB) + bg * RB + ig + 4 * v] = f2.x + f2.y;
        }
        __syncthreads();                                  // the ONE barrier

        // ---- k-reduce + h update + tanh (critical path, minimal) ----
        float s = 0.f;
        #pragma unroll
        for (int k = 0; k < KW; ++k) s += redw[k * (BS * RB) + b * RB + i];
        h = h * (1.0f - DTC) + DTC * (s + vt * bmv);
        const float th = fast_tanh(h);

        // ---- publish th + RELEASE ----
        if (t < T_STEPS - 1)
            __stcg(&g_th[p][b0 + b][i0 + i], th);
        __syncwarp();
        fence_gpu();
        if (lane == 0) red_add_gpu(fOwn, 1);

        // ---- post-release: readout partial (16-lane subgroup reduce) ----
        float c = th * wrv;
        c += __shfl_xor_sync(0xffffffffu, c, 8);
        c += __shfl_xor_sync(0xffffffffu, c, 4);
        c += __shfl_xor_sync(0xffffffffu, c, 2);
        c += __shfl_xor_sync(0xffffffffu, c, 1);
        if ((lane & 15) == 0)
            __stcg(&g_part[t & 3][grp][rank][b], c);

        // ---- post-release: rotating out-writer (rank t&31, warp 0) ----
        if (t >= 2 && w == 0 && rank == (t & 31)) {
            const float* gp = &g_part[(t - 2) & 3][grp][0][0];  // [NR][BS]
            const int bq = lane >> 2, kq = lane & 3;
            float sres = 0.f;
            #pragma unroll
            for (int m = 0; m < 8; ++m)
                sres += __ldcg(&gp[(kq * 8 + m) * BS + bq]);
            sres += __shfl_xor_sync(0xffffffffu, sres, 1);
            sres += __shfl_xor_sync(0xffffffffu, sres, 2);
            if (kq == 0)
                out[(size_t)(b0 + bq) * T_STEPS + (t - 2)] = sres;
        }
    }

    // ---- extra release round: makes final g_part stores pollable ----
    __syncwarp();
    fence_gpu();
    if (lane == 0) red_add_gpu(fOwn, 1);

    // ---- flush: ranks 0,1 write out[:,1022] and out[:,1023] ----
    if (rank <= 1) {
        if (tid < NR) {
            const int tgt = base + 4 * T_STEPS + 4;
            while (ld_acq(&g_cnt[grp][tid][0]) < tgt) { }
        }
        __syncthreads();
        if (w == 0) {
            const int tf = T_STEPS - 2 + rank;            // 1022 or 1023
            const float* gp = &g_part[tf & 3][grp][0][0];
            const int bq = lane >> 2, kq = lane & 3;
            float sres = 0.f;
            #pragma unroll
            for (int m = 0; m < 8; ++m)
                sres += __ldcg(&gp[(kq * 8 + m) * BS + bq]);
            sres += __shfl_xor_sync(0xffffffffu, sres, 1);
            sres += __shfl_xor_sync(0xffffffffu, sres, 2);
            if (kq == 0)
                out[(size_t)(b0 + bq) * T_STEPS + tf] = sres;
        }
    }
}

extern "C" void kernel_launch(void* const* d_in, const int* in_sizes, int n_in,
                              void* d_out, int out_size) {
    const float* vel  = (const float*)d_in[0];   // [128,1024,1]
    const float* J    = (const float*)d_in[1];   // [512,512]
    const float* Bmat = (const float*)d_in[2];   // [512,1]
    const float* Wro  = (const float*)d_in[3];   // [1,512]
    float* out = (float*)d_out;                  // [128,1024,1]

    cudaFuncSetAttribute(ctrnn_r11_kernel,
                         cudaFuncAttributeMaxDynamicSharedMemorySize, SMEM_BYTES);
    ctrnn_r11_kernel<<<NCTA, NTHR, SMEM_BYTES>>>(vel, J, Bmat, Wro, out);
}

// round 13
// speedup vs baseline: 1.2900x; 1.2900x over previous
#include <cuda_runtime.h>
#include <cstdint>
#include <math.h>

// CTRNN B=128, N=512, T=1024, fp32.
// R12 = R10 (256 CTAs = 16 groups x 16 ranks, IS=32, 2 CTAs/SM, per-warp
// j-chunk exchange, warp-granular counters, ONE syncthreads/step) with the
// per-step rotating out-writer replaced by a BATCHED writer: rank (t>>4)&15
// writes 16 columns once per 16 steps (g_part depth 32). Removes the
// every-step straggler from the group's critical path.

#define T_STEPS 1024
#define BATCH   128
#define NH      512
#define DTC     0.02f

#define NR   16                 // hidden ranks (IS = 32)
#define NG   16                 // batch groups (BS = 8)
#define BS   8
#define IS   32
#define NCTA (NG * NR)          // 256
#define NTHR 256
#define KW   8                  // j-chunks, one per warp (KCH = 64)
#define KCH  64
#define LDP  516
#define RB   40                 // red row pad

// smem float offsets
#define OFF_J   0                          // 32 x 516
#define OFF_TH  (OFF_J + IS * LDP)         // 8 x 516
#define OFF_RED (OFF_TH + BS * LDP)        // [2][KW][BS][RB]
#define SMEM_FLOATS (OFF_RED + 2 * KW * BS * RB)
#define SMEM_BYTES  (SMEM_FLOATS * 4)      // 103040 B -> 2 CTAs/SM

__device__ float g_th[2][BATCH][NH];        // tanh(h) double buffer (L2)
__device__ float g_part[32][NG][NR][BS];    // readout partials, 32-deep ring
__device__ int   g_cnt[NG][NR][32];         // 128B-strided warp-publish counters

__device__ __forceinline__ unsigned long long ffma2(unsigned long long a,
                                                    unsigned long long b,
                                                    unsigned long long c) {
    unsigned long long d;
    asm("fma.rn.f32x2 %0, %1, %2, %3;" : "=l"(d) : "l"(a), "l"(b), "l"(c));
    return d;
}

__device__ __forceinline__ float2 unpack2(unsigned long long v) {
    float2 f;
    asm("mov.b64 {%0, %1}, %2;" : "=f"(f.x), "=f"(f.y) : "l"(v));
    return f;
}

__device__ __forceinline__ float fast_tanh(float x) {
    float e = __expf(2.0f * x);
    return 1.0f - __fdividef(2.0f, e + 1.0f);
}

__device__ __forceinline__ int ld_acq(const int* p) {
    int v;
    asm volatile("ld.acquire.gpu.global.s32 %0, [%1];" : "=r"(v) : "l"(p) : "memory");
    return v;
}

__device__ __forceinline__ void red_add_gpu(int* p, int v) {
    asm volatile("red.relaxed.gpu.global.add.s32 [%0], %1;" :: "l"(p), "r"(v) : "memory");
}

__device__ __forceinline__ void fence_gpu() {
    asm volatile("fence.acq_rel.gpu;" ::: "memory");
}

extern "C" __global__ void __launch_bounds__(NTHR, 2)
ctrnn_r12_kernel(const float* __restrict__ vel,
                 const float* __restrict__ J,
                 const float* __restrict__ Bmat,
                 const float* __restrict__ Wro,
                 float* __restrict__ out) {
    extern __shared__ float smem[];
    float* J_s  = smem + OFF_J;
    float* th_s = smem + OFF_TH;
    float* red  = smem + OFF_RED;   // [2][KW][BS][RB]

    const int tid  = threadIdx.x;
    const int rank = blockIdx.x & (NR - 1);
    const int grp  = blockIdx.x >> 4;
    const int b0   = grp * BS;
    const int i0   = rank * IS;

    // One-time: J slice [IS x NH] into padded smem; zero th_s (tanh(0)=0).
    for (int k4 = tid; k4 < IS * NH / 4; k4 += NTHR) {
        int idx = k4 * 4, r = idx >> 9, c = idx & 511;
        *reinterpret_cast<float4*>(J_s + r * LDP + c) =
            *reinterpret_cast<const float4*>(J + (size_t)(i0 + r) * NH + c);
    }
    for (int k4 = tid; k4 < BS * NH / 4; k4 += NTHR) {
        int idx = k4 * 4, r = idx >> 9, c = idx & 511;
        *reinterpret_cast<float4*>(th_s + r * LDP + c) = make_float4(0.f, 0.f, 0.f, 0.f);
    }
    // Monotonic counter base (all counters equal at every launch boundary).
    const int base = __ldcg(&g_cnt[grp][rank][0]);
    __syncthreads();

    const int w = tid >> 5, lane = tid & 31;
    const int bg = lane & 3, ig = lane >> 2;      // GEMM tile coords
    const int kbase = w * KCH;
    const int b = w, i = lane;                    // reduce/publish ownership
    const float bmv = Bmat[i0 + i];
    const float wrv = Wro[i0 + i];
    const int* fA = &g_cnt[grp][2 * w][0];
    const int* fB = &g_cnt[grp][2 * w + 1][0];
    int* fOwn = &g_cnt[grp][rank][0];
    float h = 0.f;

    for (int t = 0; t < T_STEPS; ++t) {
        const int p = t & 1;
        float* redw = red + p * (KW * BS * RB);

        // Prefetch vel (consumed after the barrier).
        const float vt = vel[(size_t)(b0 + b) * T_STEPS + t];

        // ---- interleaved per-warp poll + stage of j-chunk [64w, 64w+64) ----
        if (t > 0) {
            const int tgt = base + 8 * t;
            const float* src = &g_th[(t - 1) & 1][b0][0];
            while (ld_acq(fA) < tgt) { }
            float4 vA[2];
            #pragma unroll
            for (int q = 0; q < 2; ++q) {        // rank 2w's 32 j's
                int idx = lane + 32 * q;         // 0..63
                int row = idx >> 3, col = kbase + (idx & 7) * 4;
                vA[q] = __ldcg(reinterpret_cast<const float4*>(src + (size_t)row * NH + col));
            }
            while (ld_acq(fB) < tgt) { }         // overlaps vA's L2 latency
            float4 vB[2];
            #pragma unroll
            for (int q = 0; q < 2; ++q) {        // rank 2w+1's 32 j's
                int idx = lane + 32 * q;
                int row = idx >> 3, col = kbase + 32 + (idx & 7) * 4;
                vB[q] = __ldcg(reinterpret_cast<const float4*>(src + (size_t)row * NH + col));
            }
            #pragma unroll
            for (int q = 0; q < 2; ++q) {
                int idx = lane + 32 * q;
                int row = idx >> 3, colA = kbase + (idx & 7) * 4;
                *reinterpret_cast<float4*>(th_s + row * LDP + colA) = vA[q];
                *reinterpret_cast<float4*>(th_s + row * LDP + colA + 32) = vB[q];
            }
            __syncwarp();
        }

        // ---- GEMM: redw[w][b][i] = sum_{j in chunk w} th[b][j] * J[i][j]
        unsigned long long acc[2][4];
        #pragma unroll
        for (int u = 0; u < 2; ++u)
            #pragma unroll
            for (int v = 0; v < 4; ++v) acc[u][v] = 0ull;

        #pragma unroll
        for (int jt = 0; jt < KCH; jt += 4) {
            const int j = kbase + jt;
            ulonglong2 av[2], bv[4];
            #pragma unroll
            for (int u = 0; u < 2; ++u)
                av[u] = *reinterpret_cast<const ulonglong2*>(th_s + (bg + 4 * u) * LDP + j);
            #pragma unroll
            for (int v = 0; v < 4; ++v)
                bv[v] = *reinterpret_cast<const ulonglong2*>(J_s + (ig + 8 * v) * LDP + j);
            #pragma unroll
            for (int u = 0; u < 2; ++u)
                #pragma unroll
                for (int v = 0; v < 4; ++v) {
                    acc[u][v] = ffma2(av[u].x, bv[v].x, acc[u][v]);
                    acc[u][v] = ffma2(av[u].y, bv[v].y, acc[u][v]);
                }
        }
        #pragma unroll
        for (int u = 0; u < 2; ++u)
            #pragma unroll
            for (int v = 0; v < 4; ++v) {
                float2 f2 = unpack2(acc[u][v]);
                redw[w * (BS * RB) + (bg + 4 * u) * RB + (ig + 8 * v)] = f2.x + f2.y;
            }
        __syncthreads();                                  // the ONE barrier

        // ---- k-reduce + h update + tanh (critical path, minimal) ----
        float s = 0.f;
        #pragma unroll
        for (int k = 0; k < KW; ++k) s += redw[k * (BS * RB) + b * RB + i];
        h = h * (1.0f - DTC) + DTC * (s + vt * bmv);
        const float th = fast_tanh(h);

        // ---- publish th + RELEASE (nothing else in front of it) ----
        if (t < T_STEPS - 1)
            __stcg(&g_th[p][b0 + b][i0 + i], th);
        __syncwarp();
        fence_gpu();                                      // warp-level release
        if (lane == 0) red_add_gpu(fOwn, 1);

        // ---- post-release: readout partial for row b (ring slot t&31) ----
        float c = th * wrv;
        #pragma unroll
        for (int off = 16; off > 0; off >>= 1)
            c += __shfl_xor_sync(0xffffffffu, c, off);
        if (lane == 0)
            __stcg(&g_part[t & 31][grp][rank][b], c);

        // ---- post-release: BATCHED out-writer, once per 16 steps ----
        // Rank (t>>4)&15 writes cols [t-17, t-2] (clamped). All 256 threads:
        // tid = [col:4][row:3][half:1]; each (col,row) = 2 threads x 8 ranks.
        if ((t & 15) == 15 && rank == ((t >> 4) & 15)) {
            const int ci   = tid >> 4;            // 0..15
            const int col  = t - 17 + ci;
            const int row  = (tid >> 1) & 7;
            const int half = tid & 1;
            if (col >= 0) {
                const float* gp = &g_part[col & 31][grp][0][0];   // [NR][BS]
                float sres = 0.f;
                #pragma unroll
                for (int m = 0; m < 8; ++m)
                    sres += __ldcg(&gp[(half * 8 + m) * BS + row]);
                sres += __shfl_xor_sync(0xffffffffu, sres, 1);
                if (half == 0)
                    out[(size_t)(b0 + row) * T_STEPS + col] = sres;
            }
        }
    }

    // ---- extra release round: makes final g_part stores pollable ----
    __syncwarp();
    fence_gpu();
    if (lane == 0) red_add_gpu(fOwn, 1);

    // ---- flush: ranks 0,1 write out[:,1022] and out[:,1023] ----
    if (rank <= 1) {
        if (tid < NR) {
            const int tgt = base + 8 * T_STEPS + 8;
            while (ld_acq(&g_cnt[grp][tid][0]) < tgt) { }
        }
        __syncthreads();
        if (w == 0) {
            const int tf = T_STEPS - 2 + rank;            // 1022 or 1023
            const float* gp = &g_part[tf & 31][grp][0][0];
            const int bq = lane >> 2, kq = lane & 3;
            float sres = 0.f;
            #pragma unroll
            for (int m = 0; m < 4; ++m)
                sres += __ldcg(&gp[(kq * 4 + m) * BS + bq]);
            sres += __shfl_xor_sync(0xffffffffu, sres, 1);
            sres += __shfl_xor_sync(0xffffffffu, sres, 2);
            if (kq == 0)
                out[(size_t)(b0 + bq) * T_STEPS + tf] = sres;
        }
    }
}

extern "C" void kernel_launch(void* const* d_in, const int* in_sizes, int n_in,
                              void* d_out, int out_size) {
    const float* vel  = (const float*)d_in[0];   // [128,1024,1]
    const float* J    = (const float*)d_in[1];   // [512,512]
    const float* Bmat = (const float*)d_in[2];   // [512,1]
    const float* Wro  = (const float*)d_in[3];   // [1,512]
    float* out = (float*)d_out;                  // [128,1024,1]

    cudaFuncSetAttribute(ctrnn_r12_kernel,
                         cudaFuncAttributeMaxDynamicSharedMemorySize, SMEM_BYTES);
    ctrnn_r12_kernel<<<NCTA, NTHR, SMEM_BYTES>>>(vel, J, Bmat, Wro, out);
}